// round 1
// baseline (speedup 1.0000x reference)
#include <cuda_runtime.h>
#include <cuda_bf16.h>
#include <cstdint>

// ---------------------------------------------------------------------------
// MultiHeadAttention: B=2, T=2048, D=1024, H=16, HD=64
//   qkv = x @ w_qkv^T + b_qkv          [4096, 3072]
//   per (b,h): attn(q,k,v), scale 1/8  -> ctx [4096, 1024]
//   out = ctx @ w_out^T + b_out        [4096, 1024]
// All matmuls in TF32 mma.sync (fp32 accumulate).
// ---------------------------------------------------------------------------

#define B_   2
#define T_   2048
#define D_   1024
#define H_   16
#define HD_  64
#define TD3_ 3072
#define M_   (B_ * T_)   // 4096

// Scratch (allocation-free rule: __device__ globals)
__device__ float g_qkv[(size_t)M_ * TD3_];   // 48 MB
__device__ float g_ctx[(size_t)M_ * D_];     // 16 MB

__device__ __forceinline__ float tf32r(float x) {
    uint32_t u;
    asm("cvt.rna.tf32.f32 %0, %1;" : "=r"(u) : "f"(x));
    return __uint_as_float(u);
}

__device__ __forceinline__ uint32_t U(float x) { return __float_as_uint(x); }

__device__ __forceinline__ void mma8(float* c,
                                     uint32_t a0, uint32_t a1, uint32_t a2, uint32_t a3,
                                     uint32_t b0, uint32_t b1) {
    asm volatile(
        "mma.sync.aligned.m16n8k8.row.col.f32.tf32.tf32.f32 "
        "{%0,%1,%2,%3},{%4,%5,%6,%7},{%8,%9},{%0,%1,%2,%3};"
        : "+f"(c[0]), "+f"(c[1]), "+f"(c[2]), "+f"(c[3])
        : "r"(a0), "r"(a1), "r"(a2), "r"(a3), "r"(b0), "r"(b1));
}

// ---------------------------------------------------------------------------
// NT GEMM with bias: C[m,n] = sum_k A[m,k]*B[n,k] + bias[n]
// A [M,K] row-major, B [N,K] row-major. Tiles 128x128x32, 256 threads.
// Warp grid 2(M) x 4(N); warp tile 64x32 -> 4x4 m16n8 mma tiles.
// ---------------------------------------------------------------------------
#define GBK 32
#define GLDA 36   // stride: 36 % 32 = 4 -> conflict-free fragment loads

__global__ void __launch_bounds__(256, 2)
gemm_nt_bias(const float* __restrict__ A, const float* __restrict__ Bm,
             const float* __restrict__ bias, float* __restrict__ C,
             int M, int N, int K) {
    __shared__ float As[128 * GLDA];
    __shared__ float Bs[128 * GLDA];

    const int tid = threadIdx.x, lane = tid & 31, wid = tid >> 5;
    const int g = lane >> 2, t4 = lane & 3;
    const int wm = wid >> 2, wn = wid & 3;          // 2 x 4
    const int bm = blockIdx.y * 128, bn = blockIdx.x * 128;

    float acc[4][4][4];
#pragma unroll
    for (int i = 0; i < 4; i++)
#pragma unroll
        for (int j = 0; j < 4; j++)
#pragma unroll
            for (int q = 0; q < 4; q++) acc[i][j][q] = 0.f;

    for (int k0 = 0; k0 < K; k0 += GBK) {
        __syncthreads();
#pragma unroll
        for (int i = 0; i < 4; i++) {
            int idx = tid + i * 256;           // 0..1023
            int r = idx >> 3, c4 = idx & 7;    // r 0..127, c4 0..7
            float4 av = *(const float4*)(A + (size_t)(bm + r) * K + k0 + c4 * 4);
            float4 bv = *(const float4*)(Bm + (size_t)(bn + r) * K + k0 + c4 * 4);
            *(float4*)(As + r * GLDA + c4 * 4) =
                make_float4(tf32r(av.x), tf32r(av.y), tf32r(av.z), tf32r(av.w));
            *(float4*)(Bs + r * GLDA + c4 * 4) =
                make_float4(tf32r(bv.x), tf32r(bv.y), tf32r(bv.z), tf32r(bv.w));
        }
        __syncthreads();
#pragma unroll
        for (int ks = 0; ks < 4; ks++) {
            const int kk = ks * 8;
            uint32_t a[4][4], b[4][2];
#pragma unroll
            for (int mt = 0; mt < 4; mt++) {
                int r = wm * 64 + mt * 16 + g;
                a[mt][0] = U(As[r * GLDA + kk + t4]);
                a[mt][1] = U(As[(r + 8) * GLDA + kk + t4]);
                a[mt][2] = U(As[r * GLDA + kk + t4 + 4]);
                a[mt][3] = U(As[(r + 8) * GLDA + kk + t4 + 4]);
            }
#pragma unroll
            for (int nt = 0; nt < 4; nt++) {
                int n = wn * 32 + nt * 8 + g;
                b[nt][0] = U(Bs[n * GLDA + kk + t4]);
                b[nt][1] = U(Bs[n * GLDA + kk + t4 + 4]);
            }
#pragma unroll
            for (int mt = 0; mt < 4; mt++)
#pragma unroll
                for (int nt = 0; nt < 4; nt++)
                    mma8(acc[mt][nt], a[mt][0], a[mt][1], a[mt][2], a[mt][3],
                         b[nt][0], b[nt][1]);
        }
    }

#pragma unroll
    for (int mt = 0; mt < 4; mt++)
#pragma unroll
        for (int nt = 0; nt < 4; nt++) {
            int r = bm + wm * 64 + mt * 16 + g;
            int c = bn + wn * 32 + nt * 8 + 2 * t4;
            float bz0 = bias[c], bz1 = bias[c + 1];
            *(float2*)(C + (size_t)r * N + c) =
                make_float2(acc[mt][nt][0] + bz0, acc[mt][nt][1] + bz1);
            *(float2*)(C + (size_t)(r + 8) * N + c) =
                make_float2(acc[mt][nt][2] + bz0, acc[mt][nt][3] + bz1);
        }
}

// ---------------------------------------------------------------------------
// Flash attention. Per block: one (b, h, 64-row q tile). 256 threads, 8 warps.
// KV tile 64. S (64x64) staged in SMEM, aliased over the K tile.
// SMEM strides: Q/K/S = 68 (A-op & n-indexed B-op conflict-free),
//               V = 72 (k-indexed B-op conflict-free).
// ---------------------------------------------------------------------------
#define FA_SMEM_FLOATS (64 * 68 + 64 * 68 + 64 * 72 + 128)
#define FA_SMEM_BYTES  (FA_SMEM_FLOATS * 4)

__global__ void __launch_bounds__(256, 2)
flash_attn(const float* __restrict__ qkv, float* __restrict__ ctx) {
    extern __shared__ float sm[];
    float* Qs = sm;                      // [64][68]
    float* KS = sm + 64 * 68;            // [64][68]  K tile, then S/P tile
    float* Vs = KS + 64 * 68;            // [64][72]
    float* scaleF = Vs + 64 * 72;        // [64]
    float* rowL = scaleF + 64;           // [64]

    const int qt = blockIdx.x;
    const int bh = blockIdx.y;
    const int b = bh >> 4, h = bh & 15;
    const int tid = threadIdx.x, lane = tid & 31, wid = tid >> 5;
    const int g = lane >> 2, t4 = lane & 3;
    const int wm = wid >> 2, wn = wid & 3;      // 2 x 4: warp tile 32(M) x 16(N)
    const int srow = tid >> 2, spart = tid & 3; // softmax: 4 threads per row

    const float* qb = qkv + (size_t)(b * T_ + qt * 64) * TD3_ + h * HD_;
    const float* kb = qkv + (size_t)(b * T_) * TD3_ + D_ + h * HD_;
    const float* vb = kb + D_;

    // Load Q (pre-scaled by 1/sqrt(HD)=0.125, tf32-rounded)
#pragma unroll
    for (int i = 0; i < 4; i++) {
        int idx = tid + i * 256;
        int r = idx >> 4, c4 = idx & 15;
        float4 v = *(const float4*)(qb + (size_t)r * TD3_ + c4 * 4);
        *(float4*)(Qs + r * 68 + c4 * 4) =
            make_float4(tf32r(v.x * 0.125f), tf32r(v.y * 0.125f),
                        tf32r(v.z * 0.125f), tf32r(v.w * 0.125f));
    }

    float O[2][2][4];
#pragma unroll
    for (int i = 0; i < 2; i++)
#pragma unroll
        for (int j = 0; j < 2; j++)
#pragma unroll
            for (int q = 0; q < 4; q++) O[i][j][q] = 0.f;
    float m_prev = -1e30f, l_prev = 0.f;

    for (int j = 0; j < T_ / 64; j++) {
        __syncthreads();  // prev iter's mma2 reads of KS/Vs are done
#pragma unroll
        for (int i = 0; i < 4; i++) {
            int idx = tid + i * 256;
            int r = idx >> 4, c4 = idx & 15;
            float4 kv = *(const float4*)(kb + (size_t)(j * 64 + r) * TD3_ + c4 * 4);
            float4 vv = *(const float4*)(vb + (size_t)(j * 64 + r) * TD3_ + c4 * 4);
            *(float4*)(KS + r * 68 + c4 * 4) =
                make_float4(tf32r(kv.x), tf32r(kv.y), tf32r(kv.z), tf32r(kv.w));
            *(float4*)(Vs + r * 72 + c4 * 4) =
                make_float4(tf32r(vv.x), tf32r(vv.y), tf32r(vv.z), tf32r(vv.w));
        }
        __syncthreads();

        // S = Q @ K^T  (M=64 q rows, N=64 kv cols, K=HD=64)
        float S[2][2][4];
#pragma unroll
        for (int i = 0; i < 2; i++)
#pragma unroll
            for (int jj = 0; jj < 2; jj++)
#pragma unroll
                for (int q = 0; q < 4; q++) S[i][jj][q] = 0.f;
#pragma unroll
        for (int ks = 0; ks < 8; ks++) {
            const int kk = ks * 8;
            uint32_t a[2][4], bb[2][2];
#pragma unroll
            for (int mt = 0; mt < 2; mt++) {
                int r = wm * 32 + mt * 16 + g;
                a[mt][0] = U(Qs[r * 68 + kk + t4]);
                a[mt][1] = U(Qs[(r + 8) * 68 + kk + t4]);
                a[mt][2] = U(Qs[r * 68 + kk + t4 + 4]);
                a[mt][3] = U(Qs[(r + 8) * 68 + kk + t4 + 4]);
            }
#pragma unroll
            for (int nt = 0; nt < 2; nt++) {
                int n = wn * 16 + nt * 8 + g;
                bb[nt][0] = U(KS[n * 68 + kk + t4]);
                bb[nt][1] = U(KS[n * 68 + kk + t4 + 4]);
            }
#pragma unroll
            for (int mt = 0; mt < 2; mt++)
#pragma unroll
                for (int nt = 0; nt < 2; nt++)
                    mma8(S[mt][nt], a[mt][0], a[mt][1], a[mt][2], a[mt][3],
                         bb[nt][0], bb[nt][1]);
        }
        __syncthreads();  // everyone done reading K before S overwrites it

        // Write S tile (stride 68)
#pragma unroll
        for (int mt = 0; mt < 2; mt++)
#pragma unroll
            for (int nt = 0; nt < 2; nt++) {
                int r = wm * 32 + mt * 16 + g;
                int c = wn * 16 + nt * 8 + 2 * t4;
                *(float2*)(KS + r * 68 + c) = make_float2(S[mt][nt][0], S[mt][nt][1]);
                *(float2*)(KS + (r + 8) * 68 + c) = make_float2(S[mt][nt][2], S[mt][nt][3]);
            }
        __syncthreads();

        // Online softmax: 4 threads per row, 16 cols each
        float* Sr = KS + srow * 68 + spart * 16;
        float mloc = -1e30f;
#pragma unroll
        for (int q = 0; q < 16; q++) mloc = fmaxf(mloc, Sr[q]);
        mloc = fmaxf(mloc, __shfl_xor_sync(0xffffffffu, mloc, 1));
        mloc = fmaxf(mloc, __shfl_xor_sync(0xffffffffu, mloc, 2));
        float m_new = fmaxf(m_prev, mloc);
        float sc = __expf(m_prev - m_new);
        float sl = 0.f;
#pragma unroll
        for (int q = 0; q < 16; q++) {
            float p = __expf(Sr[q] - m_new);
            Sr[q] = tf32r(p);
            sl += p;
        }
        sl += __shfl_xor_sync(0xffffffffu, sl, 1);
        sl += __shfl_xor_sync(0xffffffffu, sl, 2);
        l_prev = l_prev * sc + sl;
        m_prev = m_new;
        if (spart == 0) scaleF[srow] = sc;
        __syncthreads();

        // Rescale O accumulators
#pragma unroll
        for (int mt = 0; mt < 2; mt++) {
            int r = wm * 32 + mt * 16 + g;
            float s0 = scaleF[r], s1 = scaleF[r + 8];
#pragma unroll
            for (int nt = 0; nt < 2; nt++) {
                O[mt][nt][0] *= s0; O[mt][nt][1] *= s0;
                O[mt][nt][2] *= s1; O[mt][nt][3] *= s1;
            }
        }

        // O += P @ V  (M=64 q rows, N=64 hd cols, K=64 kv)
#pragma unroll
        for (int ks = 0; ks < 8; ks++) {
            const int kk = ks * 8;
            uint32_t a[2][4], bb[2][2];
#pragma unroll
            for (int mt = 0; mt < 2; mt++) {
                int r = wm * 32 + mt * 16 + g;
                a[mt][0] = U(KS[r * 68 + kk + t4]);
                a[mt][1] = U(KS[(r + 8) * 68 + kk + t4]);
                a[mt][2] = U(KS[r * 68 + kk + t4 + 4]);
                a[mt][3] = U(KS[(r + 8) * 68 + kk + t4 + 4]);
            }
#pragma unroll
            for (int nt = 0; nt < 2; nt++) {
                int n = wn * 16 + nt * 8 + g;
                bb[nt][0] = U(Vs[(kk + t4) * 72 + n]);
                bb[nt][1] = U(Vs[(kk + t4 + 4) * 72 + n]);
            }
#pragma unroll
            for (int mt = 0; mt < 2; mt++)
#pragma unroll
                for (int nt = 0; nt < 2; nt++)
                    mma8(O[mt][nt], a[mt][0], a[mt][1], a[mt][2], a[mt][3],
                         bb[nt][0], bb[nt][1]);
        }
    }

    if (spart == 0) rowL[srow] = l_prev;
    __syncthreads();

    // Epilogue: O / l -> ctx [B,T,D]
#pragma unroll
    for (int mt = 0; mt < 2; mt++)
#pragma unroll
        for (int nt = 0; nt < 2; nt++) {
            int r = wm * 32 + mt * 16 + g;
            int c = wn * 16 + nt * 8 + 2 * t4;
            float i0 = 1.f / rowL[r];
            float i1 = 1.f / rowL[r + 8];
            size_t o0 = (size_t)(b * T_ + qt * 64 + r) * D_ + h * HD_ + c;
            *(float2*)(ctx + o0) = make_float2(O[mt][nt][0] * i0, O[mt][nt][1] * i0);
            *(float2*)(ctx + o0 + (size_t)8 * D_) =
                make_float2(O[mt][nt][2] * i1, O[mt][nt][3] * i1);
        }
}

// ---------------------------------------------------------------------------
extern "C" void kernel_launch(void* const* d_in, const int* in_sizes, int n_in,
                              void* d_out, int out_size) {
    (void)in_sizes; (void)n_in; (void)out_size;
    const float* x     = (const float*)d_in[0];
    const float* w_qkv = (const float*)d_in[1];
    const float* b_qkv = (const float*)d_in[2];
    const float* w_out = (const float*)d_in[3];
    const float* b_out = (const float*)d_in[4];
    float* out = (float*)d_out;

    float *qkv_ptr, *ctx_ptr;
    cudaGetSymbolAddress((void**)&qkv_ptr, g_qkv);
    cudaGetSymbolAddress((void**)&ctx_ptr, g_ctx);
    cudaFuncSetAttribute((const void*)flash_attn,
                         cudaFuncAttributeMaxDynamicSharedMemorySize, FA_SMEM_BYTES);

    // 1) QKV projection: [4096,1024] x [3072,1024]^T + bias
    gemm_nt_bias<<<dim3(TD3_ / 128, M_ / 128), 256>>>(x, w_qkv, b_qkv, qkv_ptr,
                                                      M_, TD3_, D_);
    // 2) attention: grid (q-tiles, B*H)
    flash_attn<<<dim3(T_ / 64, B_ * H_), 256, FA_SMEM_BYTES>>>(qkv_ptr, ctx_ptr);
    // 3) output projection: [4096,1024] x [1024,1024]^T + bias
    gemm_nt_bias<<<dim3(D_ / 128, M_ / 128), 256>>>(ctx_ptr, w_out, b_out, out,
                                                    M_, D_, D_);
}

// round 2
// speedup vs baseline: 1.1650x; 1.1650x over previous
#include <cuda_runtime.h>
#include <cstdint>

#define B_   2
#define T_   2048
#define D_   1024
#define H_   16
#define HD_  64
#define TD3_ 3072
#define M_   4096

// Scratch (allocation-free rule: __device__ globals)
__device__ float g_qkv[(size_t)M_ * TD3_];    // 48 MB (tf32, q pre-scaled)
__device__ float g_ctx[(size_t)M_ * D_];      // 16 MB (tf32)
__device__ float g_xt[(size_t)M_ * D_];       // 16 MB tf32 copy of x
__device__ float g_wqkvt[(size_t)TD3_ * D_];  // 12 MB tf32 copy of w_qkv
__device__ float g_woutt[(size_t)D_ * D_];    //  4 MB tf32 copy of w_out

__device__ __forceinline__ float tf32r(float x) {
    uint32_t u;
    asm("cvt.rna.tf32.f32 %0, %1;" : "=r"(u) : "f"(x));
    return __uint_as_float(u);
}
__device__ __forceinline__ uint32_t U(float x) { return __float_as_uint(x); }

__device__ __forceinline__ void mma8(float* c,
                                     uint32_t a0, uint32_t a1, uint32_t a2, uint32_t a3,
                                     uint32_t b0, uint32_t b1) {
    asm volatile(
        "mma.sync.aligned.m16n8k8.row.col.f32.tf32.tf32.f32 "
        "{%0,%1,%2,%3},{%4,%5,%6,%7},{%8,%9},{%0,%1,%2,%3};"
        : "+f"(c[0]), "+f"(c[1]), "+f"(c[2]), "+f"(c[3])
        : "r"(a0), "r"(a1), "r"(a2), "r"(a3), "r"(b0), "r"(b1));
}

#define CP_A16(dst, src) \
    asm volatile("cp.async.cg.shared.global [%0], [%1], 16;\n" ::"r"(dst), "l"(src))
#define CP_COMMIT() asm volatile("cp.async.commit_group;\n" ::)
#define CP_WAIT1() asm volatile("cp.async.wait_group 1;\n" ::)
#define CP_WAIT0() asm volatile("cp.async.wait_group 0;\n" ::)

// ---------------------------------------------------------------------------
// Pre-pass: fp32 -> tf32 (round-to-nearest) elementwise
// ---------------------------------------------------------------------------
__global__ void __launch_bounds__(256)
cvt_tf32_kernel(const float4* __restrict__ in, float4* __restrict__ out, int n4) {
    int i = blockIdx.x * 256 + threadIdx.x;
    if (i < n4) {
        float4 v = in[i];
        out[i] = make_float4(tf32r(v.x), tf32r(v.y), tf32r(v.z), tf32r(v.w));
    }
}

// ---------------------------------------------------------------------------
// NT GEMM + bias, cp.async 2-stage pipeline. Inputs already tf32.
// Tiles 128x128x32, 256 threads, warps 2(M) x 4(N), warp tile 64x32.
// MODE 1: out = tf32r((acc+bias) * (col<1024 ? 0.125 : 1))   (qkv buffer)
// MODE 0: out = acc + bias (final fp32 output)
// ---------------------------------------------------------------------------
#define GLDA 36
#define GSTG (2 * 128 * GLDA)              // floats per stage (A+B)
#define GEMM_SMEM_BYTES (2 * GSTG * 4)     // 73728

template <int MODE>
__global__ void __launch_bounds__(256, 2)
gemm_nt_bias(const float* __restrict__ A, const float* __restrict__ Bm,
             const float* __restrict__ bias, float* __restrict__ C,
             int M, int N, int K) {
    extern __shared__ float gsm[];
    const int tid = threadIdx.x, lane = tid & 31, wid = tid >> 5;
    const int g = lane >> 2, t4 = lane & 3;
    const int wm = wid >> 2, wn = wid & 3;
    const int bm = blockIdx.y * 128, bn = blockIdx.x * 128;

    float* Asb[2] = {gsm, gsm + GSTG};
    float* Bsb[2] = {gsm + 128 * GLDA, gsm + GSTG + 128 * GLDA};
    uint32_t sA[2], sB[2];
#pragma unroll
    for (int s = 0; s < 2; s++) {
        sA[s] = (uint32_t)__cvta_generic_to_shared(Asb[s]);
        sB[s] = (uint32_t)__cvta_generic_to_shared(Bsb[s]);
    }
    const int lr = tid >> 3, lc = (tid & 7) * 4;   // rows lr+32i, col lc

    float acc[4][4][4];
#pragma unroll
    for (int i = 0; i < 4; i++)
#pragma unroll
        for (int j = 0; j < 4; j++)
#pragma unroll
            for (int q = 0; q < 4; q++) acc[i][j][q] = 0.f;

    auto load_tile = [&](int k0, int s) {
#pragma unroll
        for (int i = 0; i < 4; i++) {
            int r = lr + i * 32;
            CP_A16(sA[s] + (uint32_t)(r * GLDA + lc) * 4,
                   A + (size_t)(bm + r) * K + k0 + lc);
            CP_A16(sB[s] + (uint32_t)(r * GLDA + lc) * 4,
                   Bm + (size_t)(bn + r) * K + k0 + lc);
        }
        CP_COMMIT();
    };

    const int nt_iters = K / 32;
    load_tile(0, 0);

    for (int it = 0; it < nt_iters; it++) {
        if (it + 1 < nt_iters) {
            load_tile((it + 1) * 32, (it + 1) & 1);
            CP_WAIT1();
        } else {
            CP_WAIT0();
        }
        __syncthreads();

        const float* As = Asb[it & 1];
        const float* Bs = Bsb[it & 1];
#pragma unroll
        for (int ks = 0; ks < 4; ks++) {
            const int kk = ks * 8;
            uint32_t a[4][4], b[4][2];
#pragma unroll
            for (int mt = 0; mt < 4; mt++) {
                int r = wm * 64 + mt * 16 + g;
                a[mt][0] = U(As[r * GLDA + kk + t4]);
                a[mt][1] = U(As[(r + 8) * GLDA + kk + t4]);
                a[mt][2] = U(As[r * GLDA + kk + t4 + 4]);
                a[mt][3] = U(As[(r + 8) * GLDA + kk + t4 + 4]);
            }
#pragma unroll
            for (int nt = 0; nt < 4; nt++) {
                int n = wn * 32 + nt * 8 + g;
                b[nt][0] = U(Bs[n * GLDA + kk + t4]);
                b[nt][1] = U(Bs[n * GLDA + kk + t4 + 4]);
            }
#pragma unroll
            for (int mt = 0; mt < 4; mt++)
#pragma unroll
                for (int nt = 0; nt < 4; nt++)
                    mma8(acc[mt][nt], a[mt][0], a[mt][1], a[mt][2], a[mt][3],
                         b[nt][0], b[nt][1]);
        }
        __syncthreads();
    }

#pragma unroll
    for (int mt = 0; mt < 4; mt++)
#pragma unroll
        for (int nt = 0; nt < 4; nt++) {
            int r = bm + wm * 64 + mt * 16 + g;
            int c = bn + wn * 32 + nt * 8 + 2 * t4;
            float bz0 = bias[c], bz1 = bias[c + 1];
            float v00 = acc[mt][nt][0] + bz0, v01 = acc[mt][nt][1] + bz1;
            float v10 = acc[mt][nt][2] + bz0, v11 = acc[mt][nt][3] + bz1;
            if (MODE == 1) {
                float s = (c < D_) ? 0.125f : 1.0f;
                v00 = tf32r(v00 * s); v01 = tf32r(v01 * s);
                v10 = tf32r(v10 * s); v11 = tf32r(v11 * s);
            }
            *(float2*)(C + (size_t)r * N + c) = make_float2(v00, v01);
            *(float2*)(C + (size_t)(r + 8) * N + c) = make_float2(v10, v11);
        }
}

// ---------------------------------------------------------------------------
// Flash attention, register-resident softmax.
// Block: 128 q-rows x one (b,h). 8 warps; warp w owns rows 16w..16w+15,
// full N=64 per warp -> softmax reductions are quad shuffles only.
// KV tiles of 64, cp.async double-buffered. Q in SMEM (stride 68).
// P -> A-fragment conversion via quad shuffles (no SMEM round trip).
// ---------------------------------------------------------------------------
#define FKS 68
#define FVS 72
#define FSTG (64 * FKS + 64 * FVS)          // 8960 floats per stage
#define FQOFF (2 * FSTG)                    // Q tile at 17920
#define FA_SMEM_BYTES ((FQOFF + 128 * FKS) * 4)   // 106496

__global__ void __launch_bounds__(256, 2)
flash_attn(const float* __restrict__ qkv, float* __restrict__ ctx) {
    extern __shared__ float fsm[];
    const int qt = blockIdx.x, bh = blockIdx.y;
    const int b = bh >> 4, h = bh & 15;
    const int tid = threadIdx.x, lane = tid & 31, wid = tid >> 5;
    const int g = lane >> 2, t4 = lane & 3;
    const int wrow = wid * 16;

    const float* qb = qkv + (size_t)(b * T_ + qt * 128) * TD3_ + h * HD_;
    const float* kb = qkv + (size_t)(b * T_) * TD3_ + D_ + h * HD_;
    const float* vb = kb + D_;

    float* Qs = fsm + FQOFF;
    uint32_t sK[2], sV[2];
#pragma unroll
    for (int s = 0; s < 2; s++) {
        sK[s] = (uint32_t)__cvta_generic_to_shared(fsm + s * FSTG);
        sV[s] = (uint32_t)__cvta_generic_to_shared(fsm + s * FSTG + 64 * FKS);
    }
    const int lr = tid >> 4, lc = (tid & 15) * 4;   // kv rows lr+16i, col lc

    // Prefetch KV tile 0
#pragma unroll
    for (int i = 0; i < 4; i++) {
        int r = lr + i * 16;
        CP_A16(sK[0] + (uint32_t)(r * FKS + lc) * 4, kb + (size_t)r * TD3_ + lc);
        CP_A16(sV[0] + (uint32_t)(r * FVS + lc) * 4, vb + (size_t)r * TD3_ + lc);
    }
    CP_COMMIT();

    // Stage Q (already tf32 + pre-scaled by 1/8 in GEMM1 epilogue)
#pragma unroll
    for (int i = 0; i < 8; i++) {
        int r = lr + i * 16;
        float4 v = *(const float4*)(qb + (size_t)r * TD3_ + lc);
        *(float4*)(Qs + r * FKS + lc) = v;
    }

    float O[8][4];
#pragma unroll
    for (int nt = 0; nt < 8; nt++)
#pragma unroll
        for (int q = 0; q < 4; q++) O[nt][q] = 0.f;
    float m0 = -1e30f, m1 = -1e30f, l0 = 0.f, l1 = 0.f;

    const int qr = wrow + g;
    const int quadbase = lane & 28;
    const int src0 = quadbase | (t4 >> 1);
    const int src1 = src0 + 2;
    const bool odd = (t4 & 1);

    for (int j = 0; j < T_ / 64; j++) {
        if (j + 1 < T_ / 64) {
            const float* kbn = kb + (size_t)((j + 1) * 64) * TD3_;
            const float* vbn = vb + (size_t)((j + 1) * 64) * TD3_;
            int s = (j + 1) & 1;
#pragma unroll
            for (int i = 0; i < 4; i++) {
                int r = lr + i * 16;
                CP_A16(sK[s] + (uint32_t)(r * FKS + lc) * 4, kbn + (size_t)r * TD3_ + lc);
                CP_A16(sV[s] + (uint32_t)(r * FVS + lc) * 4, vbn + (size_t)r * TD3_ + lc);
            }
            CP_COMMIT();
            CP_WAIT1();
        } else {
            CP_WAIT0();
        }
        __syncthreads();   // stage j ready for everyone; Q staged (iter 0)

        const float* Kt = fsm + (j & 1) * FSTG;
        const float* Vt = Kt + 64 * FKS;

        // ---- S = Q @ K^T ----
        float S[8][4];
#pragma unroll
        for (int nt = 0; nt < 8; nt++)
#pragma unroll
            for (int q = 0; q < 4; q++) S[nt][q] = 0.f;
#pragma unroll
        for (int kc = 0; kc < 8; kc++) {
            const int kk = kc * 8;
            uint32_t a0 = U(Qs[qr * FKS + kk + t4]);
            uint32_t a1 = U(Qs[(qr + 8) * FKS + kk + t4]);
            uint32_t a2 = U(Qs[qr * FKS + kk + t4 + 4]);
            uint32_t a3 = U(Qs[(qr + 8) * FKS + kk + t4 + 4]);
#pragma unroll
            for (int nt = 0; nt < 8; nt++) {
                int n = nt * 8 + g;
                uint32_t b0 = U(Kt[n * FKS + kk + t4]);
                uint32_t b1 = U(Kt[n * FKS + kk + t4 + 4]);
                mma8(S[nt], a0, a1, a2, a3, b0, b1);
            }
        }

        // ---- online softmax, fully in registers (quad reductions) ----
        float mx0 = -1e30f, mx1 = -1e30f;
#pragma unroll
        for (int nt = 0; nt < 8; nt++) {
            mx0 = fmaxf(mx0, fmaxf(S[nt][0], S[nt][1]));
            mx1 = fmaxf(mx1, fmaxf(S[nt][2], S[nt][3]));
        }
        mx0 = fmaxf(mx0, __shfl_xor_sync(0xffffffffu, mx0, 1));
        mx0 = fmaxf(mx0, __shfl_xor_sync(0xffffffffu, mx0, 2));
        mx1 = fmaxf(mx1, __shfl_xor_sync(0xffffffffu, mx1, 1));
        mx1 = fmaxf(mx1, __shfl_xor_sync(0xffffffffu, mx1, 2));
        float mn0 = fmaxf(m0, mx0), mn1 = fmaxf(m1, mx1);
        float sc0 = __expf(m0 - mn0), sc1 = __expf(m1 - mn1);
        float sl0 = 0.f, sl1 = 0.f;
#pragma unroll
        for (int nt = 0; nt < 8; nt++) {
            float p0 = __expf(S[nt][0] - mn0); sl0 += p0; S[nt][0] = tf32r(p0);
            float p1 = __expf(S[nt][1] - mn0); sl0 += p1; S[nt][1] = tf32r(p1);
            float p2 = __expf(S[nt][2] - mn1); sl1 += p2; S[nt][2] = tf32r(p2);
            float p3 = __expf(S[nt][3] - mn1); sl1 += p3; S[nt][3] = tf32r(p3);
        }
        sl0 += __shfl_xor_sync(0xffffffffu, sl0, 1);
        sl0 += __shfl_xor_sync(0xffffffffu, sl0, 2);
        sl1 += __shfl_xor_sync(0xffffffffu, sl1, 1);
        sl1 += __shfl_xor_sync(0xffffffffu, sl1, 2);
        l0 = l0 * sc0 + sl0; l1 = l1 * sc1 + sl1;
        m0 = mn0; m1 = mn1;

#pragma unroll
        for (int nt = 0; nt < 8; nt++) {
            O[nt][0] *= sc0; O[nt][1] *= sc0;
            O[nt][2] *= sc1; O[nt][3] *= sc1;
        }

        // ---- O += P @ V : P C-frag -> A-frag via quad shuffles ----
#pragma unroll
        for (int kc = 0; kc < 8; kc++) {
            float x0 = __shfl_sync(0xffffffffu, S[kc][0], src0);
            float x1 = __shfl_sync(0xffffffffu, S[kc][1], src0);
            float x2 = __shfl_sync(0xffffffffu, S[kc][0], src1);
            float x3 = __shfl_sync(0xffffffffu, S[kc][1], src1);
            float y0 = __shfl_sync(0xffffffffu, S[kc][2], src0);
            float y1 = __shfl_sync(0xffffffffu, S[kc][3], src0);
            float y2 = __shfl_sync(0xffffffffu, S[kc][2], src1);
            float y3 = __shfl_sync(0xffffffffu, S[kc][3], src1);
            uint32_t a0 = U(odd ? x1 : x0);   // row g,   col t4
            uint32_t a2 = U(odd ? x3 : x2);   // row g,   col t4+4
            uint32_t a1 = U(odd ? y1 : y0);   // row g+8, col t4
            uint32_t a3 = U(odd ? y3 : y2);   // row g+8, col t4+4
            const int kk = kc * 8;
#pragma unroll
            for (int nt = 0; nt < 8; nt++) {
                int n = nt * 8 + g;
                uint32_t b0 = U(Vt[(kk + t4) * FVS + n]);
                uint32_t b1 = U(Vt[(kk + t4 + 4) * FVS + n]);
                mma8(O[nt], a0, a1, a2, a3, b0, b1);
            }
        }
        __syncthreads();   // stage j consumed; safe to overwrite at j+2 issue
    }

    // ---- epilogue: ctx = tf32r(O / l) ----
    float il0 = 1.f / l0, il1 = 1.f / l1;
    const size_t row0 = (size_t)(b * T_ + qt * 128 + wrow + g);
#pragma unroll
    for (int nt = 0; nt < 8; nt++) {
        int c = h * HD_ + nt * 8 + 2 * t4;
        *(float2*)(ctx + row0 * D_ + c) =
            make_float2(tf32r(O[nt][0] * il0), tf32r(O[nt][1] * il0));
        *(float2*)(ctx + (row0 + 8) * D_ + c) =
            make_float2(tf32r(O[nt][2] * il1), tf32r(O[nt][3] * il1));
    }
}

// ---------------------------------------------------------------------------
extern "C" void kernel_launch(void* const* d_in, const int* in_sizes, int n_in,
                              void* d_out, int out_size) {
    (void)in_sizes; (void)n_in; (void)out_size;
    const float* x     = (const float*)d_in[0];
    const float* w_qkv = (const float*)d_in[1];
    const float* b_qkv = (const float*)d_in[2];
    const float* w_out = (const float*)d_in[3];
    const float* b_out = (const float*)d_in[4];
    float* out = (float*)d_out;

    float *qkv_p, *ctx_p, *xt_p, *wqkvt_p, *woutt_p;
    cudaGetSymbolAddress((void**)&qkv_p, g_qkv);
    cudaGetSymbolAddress((void**)&ctx_p, g_ctx);
    cudaGetSymbolAddress((void**)&xt_p, g_xt);
    cudaGetSymbolAddress((void**)&wqkvt_p, g_wqkvt);
    cudaGetSymbolAddress((void**)&woutt_p, g_woutt);

    cudaFuncSetAttribute((const void*)gemm_nt_bias<1>,
                         cudaFuncAttributeMaxDynamicSharedMemorySize, GEMM_SMEM_BYTES);
    cudaFuncSetAttribute((const void*)gemm_nt_bias<0>,
                         cudaFuncAttributeMaxDynamicSharedMemorySize, GEMM_SMEM_BYTES);
    cudaFuncSetAttribute((const void*)flash_attn,
                         cudaFuncAttributeMaxDynamicSharedMemorySize, FA_SMEM_BYTES);

    // 0) tf32 pre-conversion of inputs
    int n4x = M_ * D_ / 4, n4w1 = TD3_ * D_ / 4, n4w2 = D_ * D_ / 4;
    cvt_tf32_kernel<<<n4x / 256, 256>>>((const float4*)x, (float4*)xt_p, n4x);
    cvt_tf32_kernel<<<n4w1 / 256, 256>>>((const float4*)w_qkv, (float4*)wqkvt_p, n4w1);
    cvt_tf32_kernel<<<n4w2 / 256, 256>>>((const float4*)w_out, (float4*)woutt_p, n4w2);

    // 1) QKV projection -> tf32 qkv (q pre-scaled by 1/8)
    gemm_nt_bias<1><<<dim3(TD3_ / 128, M_ / 128), 256, GEMM_SMEM_BYTES>>>(
        xt_p, wqkvt_p, b_qkv, qkv_p, M_, TD3_, D_);
    // 2) attention -> tf32 ctx
    flash_attn<<<dim3(T_ / 128, B_ * H_), 256, FA_SMEM_BYTES>>>(qkv_p, ctx_p);
    // 3) output projection -> fp32 out
    gemm_nt_bias<0><<<dim3(D_ / 128, M_ / 128), 256, GEMM_SMEM_BYTES>>>(
        ctx_p, woutt_p, b_out, out, M_, D_, D_);
}

// round 4
// speedup vs baseline: 2.4257x; 2.0822x over previous
#include <cuda_runtime.h>
#include <cuda_fp16.h>
#include <cstdint>

#define B_   2
#define T_   2048
#define D_   1024
#define H_   16
#define HD_  64
#define TD3_ 3072
#define M_   4096

// Scratch (allocation-free rule: __device__ globals), all fp16
__device__ __half g_qkv[(size_t)M_ * TD3_];    // 24 MB (q pre-scaled by 1/8)
__device__ __half g_ctx[(size_t)M_ * D_];      //  8 MB
__device__ __half g_xh[(size_t)M_ * D_];       //  8 MB
__device__ __half g_wqkvh[(size_t)TD3_ * D_];  //  6 MB
__device__ __half g_wouth[(size_t)D_ * D_];    //  2 MB

__device__ __forceinline__ uint32_t H2(float lo, float hi) {
    __half2 h = __floats2half2_rn(lo, hi);
    return *(uint32_t*)&h;
}

#define MMA16(c, a0, a1, a2, a3, b0, b1)                                       \
    asm volatile(                                                              \
        "mma.sync.aligned.m16n8k16.row.col.f32.f16.f16.f32 "                   \
        "{%0,%1,%2,%3},{%4,%5,%6,%7},{%8,%9},{%0,%1,%2,%3};"                   \
        : "+f"((c)[0]), "+f"((c)[1]), "+f"((c)[2]), "+f"((c)[3])               \
        : "r"(a0), "r"(a1), "r"(a2), "r"(a3), "r"(b0), "r"(b1))

#define CP_A16(dst, src) \
    asm volatile("cp.async.cg.shared.global [%0], [%1], 16;\n" ::"r"(dst), "l"(src))
#define CP_COMMIT() asm volatile("cp.async.commit_group;\n" ::)
#define CP_WAIT2() asm volatile("cp.async.wait_group 2;\n" ::)
#define CP_WAIT1() asm volatile("cp.async.wait_group 1;\n" ::)
#define CP_WAIT0() asm volatile("cp.async.wait_group 0;\n" ::)

#define LDMX4T(r0, r1, r2, r3, addr)                                           \
    asm volatile("ldmatrix.sync.aligned.m8n8.x4.trans.shared.b16 "             \
                 "{%0,%1,%2,%3}, [%4];"                                        \
                 : "=r"(r0), "=r"(r1), "=r"(r2), "=r"(r3) : "r"(addr))

// ---------------------------------------------------------------------------
// Pre-pass: fp32 -> fp16 (RN) elementwise
// ---------------------------------------------------------------------------
__global__ void __launch_bounds__(256)
cvt_h_kernel(const float4* __restrict__ in, uint2* __restrict__ out, int n4) {
    int i = blockIdx.x * 256 + threadIdx.x;
    if (i < n4) {
        float4 v = in[i];
        out[i] = make_uint2(H2(v.x, v.y), H2(v.z, v.w));
    }
}

// ---------------------------------------------------------------------------
// fp16 NT GEMM + bias: C[m,n] = sum_k A[m,k]*B[n,k] + bias[n]
// A [M,K] half row-major, B [N,K] half row-major, bias fp32.
// CTA tile 128(M) x 256(N), K-tile 64 halfs, 3-stage cp.async, 256 thr.
// Warps 2(M) x 4(N), warp tile 64x64 -> 4x8 m16n8k16 tiles (LDS/MMA = 1.0).
// MODE 1: qkv epilogue: half out, cols<1024 scaled by 0.125.
// MODE 0: fp32 out.
// SMEM viewed as float(=half2) rows: stride 36 floats (72 halfs), swizzle-free.
// ---------------------------------------------------------------------------
#define GLDA 36                               // floats (= half2 units)
#define GSTG ((128 + 256) * GLDA)             // floats per stage = 13824
#define GSTAGES 3
#define GEMM_SMEM_BYTES (GSTAGES * GSTG * 4)  // 165888

template <int MODE>
__global__ void __launch_bounds__(256, 1)
gemm_h(const __half* __restrict__ A, const __half* __restrict__ Bm,
       const float* __restrict__ bias, void* __restrict__ Cv,
       int Mdim, int Ndim, int Kdim) {
    extern __shared__ float gsm[];
    const int tid = threadIdx.x, lane = tid & 31, wid = tid >> 5;
    const int g = lane >> 2, t4 = lane & 3;
    const int wm = wid >> 2, wn = wid & 3;            // 2 x 4
    const int bm = blockIdx.y * 128, bn = blockIdx.x * 256;

    uint32_t sbase = (uint32_t)__cvta_generic_to_shared(gsm);
    const int ar = tid >> 3;                 // 0..31
    const int acb = (tid & 7) * 16;          // byte within 128B row

    // load K-tile (64 halfs wide) into stage s
    auto load_tile = [&](int k0, int s) {
        const uint32_t stA = sbase + (uint32_t)(s * GSTG) * 4;
        const uint32_t stB = stA + 128u * GLDA * 4;
        const __half* Ap = A + (size_t)(bm + ar) * Kdim + k0 + (acb >> 1);
        const __half* Bp = Bm + (size_t)(bn + ar) * Kdim + k0 + (acb >> 1);
#pragma unroll
        for (int i = 0; i < 4; i++)
            CP_A16(stA + (uint32_t)(ar + 32 * i) * (GLDA * 4) + acb,
                   Ap + (size_t)(32 * i) * Kdim);
#pragma unroll
        for (int i = 0; i < 8; i++)
            CP_A16(stB + (uint32_t)(ar + 32 * i) * (GLDA * 4) + acb,
                   Bp + (size_t)(32 * i) * Kdim);
        CP_COMMIT();
    };

    float acc[4][8][4];
#pragma unroll
    for (int i = 0; i < 4; i++)
#pragma unroll
        for (int j = 0; j < 8; j++)
#pragma unroll
            for (int q = 0; q < 4; q++) acc[i][j][q] = 0.f;

    const int nt_iters = Kdim >> 6;          // K / 64
    load_tile(0, 0);
    if (nt_iters > 1) load_tile(64, 1);
    if (nt_iters > 2) load_tile(128, 2);

    for (int it = 0; it < nt_iters; it++) {
        if (it + 3 <= nt_iters) { if (it + 3 == nt_iters) CP_WAIT2(); else CP_WAIT2(); }
        else if (it + 2 == nt_iters) CP_WAIT1();
        else CP_WAIT0();
        __syncthreads();

        const float* As = gsm + (it % 3) * GSTG;
        const float* Bs = As + 128 * GLDA;
#pragma unroll
        for (int ks = 0; ks < 4; ks++) {     // k16 slabs
            const int kk = ks * 8;
            uint32_t a[4][4], b[8][2];
#pragma unroll
            for (int mt = 0; mt < 4; mt++) {
                int r = wm * 64 + mt * 16 + g;
                a[mt][0] = *(const uint32_t*)(As + r * GLDA + kk + t4);
                a[mt][1] = *(const uint32_t*)(As + (r + 8) * GLDA + kk + t4);
                a[mt][2] = *(const uint32_t*)(As + r * GLDA + kk + t4 + 4);
                a[mt][3] = *(const uint32_t*)(As + (r + 8) * GLDA + kk + t4 + 4);
            }
#pragma unroll
            for (int nt = 0; nt < 8; nt++) {
                int n = wn * 64 + nt * 8 + g;
                b[nt][0] = *(const uint32_t*)(Bs + n * GLDA + kk + t4);
                b[nt][1] = *(const uint32_t*)(Bs + n * GLDA + kk + t4 + 4);
            }
#pragma unroll
            for (int mt = 0; mt < 4; mt++)
#pragma unroll
                for (int nt = 0; nt < 8; nt++)
                    MMA16(acc[mt][nt], a[mt][0], a[mt][1], a[mt][2], a[mt][3],
                          b[nt][0], b[nt][1]);
        }
        __syncthreads();
        if (it + 3 < nt_iters) load_tile((it + 3) * 64, (it + 3) % 3);
    }

    // Epilogue
#pragma unroll
    for (int mt = 0; mt < 4; mt++)
#pragma unroll
        for (int nt = 0; nt < 8; nt++) {
            int r = bm + wm * 64 + mt * 16 + g;
            int c = bn + wn * 64 + nt * 8 + 2 * t4;
            float bz0 = bias[c], bz1 = bias[c + 1];
            float v00 = acc[mt][nt][0] + bz0, v01 = acc[mt][nt][1] + bz1;
            float v10 = acc[mt][nt][2] + bz0, v11 = acc[mt][nt][3] + bz1;
            if (MODE == 1) {
                const float sc = (bn < D_) ? 0.125f : 1.0f;
                __half* Ch = (__half*)Cv;
                *(uint32_t*)(Ch + (size_t)r * Ndim + c) = H2(v00 * sc, v01 * sc);
                *(uint32_t*)(Ch + (size_t)(r + 8) * Ndim + c) = H2(v10 * sc, v11 * sc);
            } else {
                float* Cf = (float*)Cv;
                *(float2*)(Cf + (size_t)r * Ndim + c) = make_float2(v00, v01);
                *(float2*)(Cf + (size_t)(r + 8) * Ndim + c) = make_float2(v10, v11);
            }
        }
}

// ---------------------------------------------------------------------------
// fp16 flash attention. Block: 128 q-rows x one (b,h). 8 warps; warp w owns
// rows 16w..16w+15, full N=64 -> softmax = quad shuffles only. KV tile 64,
// cp.async double-buffered. P C-frag == A-frag (no transpose). V via
// ldmatrix.x4.trans. Row stride 72 halfs (36 floats), conflict-free.
// ---------------------------------------------------------------------------
#define FSH 72                                    // halfs per row
#define FSTGH (2 * 64 * FSH)                      // K+V halfs per stage = 9216
#define FQOFFH (2 * FSTGH)                        // Q at 18432 halfs
#define FA_SMEM_BYTES ((FQOFFH + 128 * FSH) * 2)  // 55296

__global__ void __launch_bounds__(256, 2)
flash_attn_h(const __half* __restrict__ qkv, __half* __restrict__ ctx) {
    extern __shared__ __half fsmh[];
    const int qt = blockIdx.x, bh = blockIdx.y;
    const int b = bh >> 4, h = bh & 15;
    const int tid = threadIdx.x, lane = tid & 31, wid = tid >> 5;
    const int g = lane >> 2, t4 = lane & 3;
    const int wrow = wid * 16;

    const __half* qb = qkv + (size_t)(b * T_ + qt * 128) * TD3_ + h * HD_;
    const __half* kb = qkv + (size_t)(b * T_) * TD3_ + D_ + h * HD_;
    const __half* vb = kb + D_;

    const uint32_t sb = (uint32_t)__cvta_generic_to_shared(fsmh);
    const uint32_t qsb = sb + FQOFFH * 2;
    const int cr = tid >> 3;                  // 0..31
    const int ccb = (tid & 7) * 16;           // byte col

    // KV tile loader (rows cr, cr+32)
    auto load_kv = [&](int j, int s) {
        const uint32_t ksb = sb + (uint32_t)(s * FSTGH) * 2;
        const uint32_t vsb = ksb + 64u * FSH * 2;
        const __half* kp = kb + (size_t)(j * 64 + cr) * TD3_ + (ccb >> 1);
        const __half* vp = vb + (size_t)(j * 64 + cr) * TD3_ + (ccb >> 1);
#pragma unroll
        for (int i = 0; i < 2; i++) {
            CP_A16(ksb + (uint32_t)(cr + 32 * i) * (FSH * 2) + ccb,
                   kp + (size_t)(32 * i) * TD3_);
            CP_A16(vsb + (uint32_t)(cr + 32 * i) * (FSH * 2) + ccb,
                   vp + (size_t)(32 * i) * TD3_);
        }
        CP_COMMIT();
    };

    load_kv(0, 0);

    // Stage Q (plain copies, once)
#pragma unroll
    for (int i = 0; i < 4; i++) {
        int r = cr + 32 * i;
        uint4 v = *(const uint4*)(qb + (size_t)r * TD3_ + (ccb >> 1));
        *(uint4*)((char*)fsmh + FQOFFH * 2 + r * (FSH * 2) + ccb) = v;
    }

    float O[8][4];
#pragma unroll
    for (int nt = 0; nt < 8; nt++)
#pragma unroll
        for (int q = 0; q < 4; q++) O[nt][q] = 0.f;
    float m0 = -1e30f, m1 = -1e30f, l0 = 0.f, l1 = 0.f;

    const int qr = wrow + g;
    const float* Qf = (const float*)fsmh + FQOFFH / 2;   // float view of Q

    for (int j = 0; j < T_ / 64; j++) {
        if (j + 1 < T_ / 64) { load_kv(j + 1, (j + 1) & 1); CP_WAIT1(); }
        else CP_WAIT0();
        __syncthreads();

        const float* Kf = (const float*)fsmh + (j & 1) * (FSTGH / 2);
        const uint32_t vsb = sb + (uint32_t)((j & 1) * FSTGH + 64 * FSH) * 2;

        // ---- S = Q @ K^T  (4 k16 slabs) ----
        float S[8][4];
#pragma unroll
        for (int nt = 0; nt < 8; nt++)
#pragma unroll
            for (int q = 0; q < 4; q++) S[nt][q] = 0.f;
#pragma unroll
        for (int ks = 0; ks < 4; ks++) {
            const int kk = ks * 8;
            uint32_t a0 = *(const uint32_t*)(Qf + qr * (FSH / 2) + kk + t4);
            uint32_t a1 = *(const uint32_t*)(Qf + (qr + 8) * (FSH / 2) + kk + t4);
            uint32_t a2 = *(const uint32_t*)(Qf + qr * (FSH / 2) + kk + t4 + 4);
            uint32_t a3 = *(const uint32_t*)(Qf + (qr + 8) * (FSH / 2) + kk + t4 + 4);
#pragma unroll
            for (int nt = 0; nt < 8; nt++) {
                int n = nt * 8 + g;
                uint32_t b0 = *(const uint32_t*)(Kf + n * (FSH / 2) + kk + t4);
                uint32_t b1 = *(const uint32_t*)(Kf + n * (FSH / 2) + kk + t4 + 4);
                MMA16(S[nt], a0, a1, a2, a3, b0, b1);
            }
        }

        // ---- online softmax in registers ----
        float mx0 = -1e30f, mx1 = -1e30f;
#pragma unroll
        for (int nt = 0; nt < 8; nt++) {
            mx0 = fmaxf(mx0, fmaxf(S[nt][0], S[nt][1]));
            mx1 = fmaxf(mx1, fmaxf(S[nt][2], S[nt][3]));
        }
        mx0 = fmaxf(mx0, __shfl_xor_sync(0xffffffffu, mx0, 1));
        mx0 = fmaxf(mx0, __shfl_xor_sync(0xffffffffu, mx0, 2));
        mx1 = fmaxf(mx1, __shfl_xor_sync(0xffffffffu, mx1, 1));
        mx1 = fmaxf(mx1, __shfl_xor_sync(0xffffffffu, mx1, 2));
        float mn0 = fmaxf(m0, mx0), mn1 = fmaxf(m1, mx1);
        float sc0 = __expf(m0 - mn0), sc1 = __expf(m1 - mn1);
        float sl0 = 0.f, sl1 = 0.f;
#pragma unroll
        for (int nt = 0; nt < 8; nt++) {
            float p0 = __expf(S[nt][0] - mn0); sl0 += p0; S[nt][0] = p0;
            float p1 = __expf(S[nt][1] - mn0); sl0 += p1; S[nt][1] = p1;
            float p2 = __expf(S[nt][2] - mn1); sl1 += p2; S[nt][2] = p2;
            float p3 = __expf(S[nt][3] - mn1); sl1 += p3; S[nt][3] = p3;
        }
        sl0 += __shfl_xor_sync(0xffffffffu, sl0, 1);
        sl0 += __shfl_xor_sync(0xffffffffu, sl0, 2);
        sl1 += __shfl_xor_sync(0xffffffffu, sl1, 1);
        sl1 += __shfl_xor_sync(0xffffffffu, sl1, 2);
        l0 = l0 * sc0 + sl0; l1 = l1 * sc1 + sl1;
        m0 = mn0; m1 = mn1;

#pragma unroll
        for (int nt = 0; nt < 8; nt++) {
            O[nt][0] *= sc0; O[nt][1] *= sc0;
            O[nt][2] *= sc1; O[nt][3] *= sc1;
        }

        // ---- O += P @ V : P C-frag == A-frag (fp16), V via ldmatrix.trans ----
        const int i8 = lane & 7, seg = lane >> 3;
        const int vrow_off = ((seg & 1) ? 8 : 0) + i8;
        const int vcol_off = (seg & 2) ? 8 : 0;
#pragma unroll
        for (int kc = 0; kc < 4; kc++) {
            uint32_t a0 = H2(S[2 * kc][0], S[2 * kc][1]);
            uint32_t a1 = H2(S[2 * kc][2], S[2 * kc][3]);
            uint32_t a2 = H2(S[2 * kc + 1][0], S[2 * kc + 1][1]);
            uint32_t a3 = H2(S[2 * kc + 1][2], S[2 * kc + 1][3]);
#pragma unroll
            for (int nt2 = 0; nt2 < 4; nt2++) {
                uint32_t r0, r1, r2, r3;
                uint32_t addr = vsb +
                    (uint32_t)((16 * kc + vrow_off) * FSH + nt2 * 16 + vcol_off) * 2;
                LDMX4T(r0, r1, r2, r3, addr);
                MMA16(O[2 * nt2], a0, a1, a2, a3, r0, r1);
                MMA16(O[2 * nt2 + 1], a0, a1, a2, a3, r2, r3);
            }
        }
        __syncthreads();
    }

    // ---- epilogue: ctx = half(O / l) ----
    float il0 = 1.f / l0, il1 = 1.f / l1;
    const size_t row0 = (size_t)(b * T_ + qt * 128 + wrow + g);
#pragma unroll
    for (int nt = 0; nt < 8; nt++) {
        int c = h * HD_ + nt * 8 + 2 * t4;
        *(uint32_t*)(ctx + row0 * D_ + c) = H2(O[nt][0] * il0, O[nt][1] * il0);
        *(uint32_t*)(ctx + (row0 + 8) * D_ + c) = H2(O[nt][2] * il1, O[nt][3] * il1);
    }
}

// ---------------------------------------------------------------------------
extern "C" void kernel_launch(void* const* d_in, const int* in_sizes, int n_in,
                              void* d_out, int out_size) {
    (void)in_sizes; (void)n_in; (void)out_size;
    const float* x     = (const float*)d_in[0];
    const float* w_qkv = (const float*)d_in[1];
    const float* b_qkv = (const float*)d_in[2];
    const float* w_out = (const float*)d_in[3];
    const float* b_out = (const float*)d_in[4];
    float* out = (float*)d_out;

    __half *qkv_p, *ctx_p, *xh_p, *wqkvh_p, *wouth_p;
    cudaGetSymbolAddress((void**)&qkv_p, g_qkv);
    cudaGetSymbolAddress((void**)&ctx_p, g_ctx);
    cudaGetSymbolAddress((void**)&xh_p, g_xh);
    cudaGetSymbolAddress((void**)&wqkvh_p, g_wqkvh);
    cudaGetSymbolAddress((void**)&wouth_p, g_wouth);

    cudaFuncSetAttribute((const void*)gemm_h<1>,
                         cudaFuncAttributeMaxDynamicSharedMemorySize, GEMM_SMEM_BYTES);
    cudaFuncSetAttribute((const void*)gemm_h<0>,
                         cudaFuncAttributeMaxDynamicSharedMemorySize, GEMM_SMEM_BYTES);
    cudaFuncSetAttribute((const void*)flash_attn_h,
                         cudaFuncAttributeMaxDynamicSharedMemorySize, FA_SMEM_BYTES);

    // 0) fp32 -> fp16 pre-conversion
    int n4x = M_ * D_ / 4, n4w1 = TD3_ * D_ / 4, n4w2 = D_ * D_ / 4;
    cvt_h_kernel<<<n4x / 256, 256>>>((const float4*)x, (uint2*)xh_p, n4x);
    cvt_h_kernel<<<n4w1 / 256, 256>>>((const float4*)w_qkv, (uint2*)wqkvh_p, n4w1);
    cvt_h_kernel<<<n4w2 / 256, 256>>>((const float4*)w_out, (uint2*)wouth_p, n4w2);

    // 1) QKV projection -> half qkv (q pre-scaled by 1/8)
    gemm_h<1><<<dim3(TD3_ / 256, M_ / 128), 256, GEMM_SMEM_BYTES>>>(
        xh_p, wqkvh_p, b_qkv, qkv_p, M_, TD3_, D_);
    // 2) attention -> half ctx
    flash_attn_h<<<dim3(T_ / 128, B_ * H_), 256, FA_SMEM_BYTES>>>(qkv_p, ctx_p);
    // 3) output projection -> fp32 out
    gemm_h<0><<<dim3(D_ / 256, M_ / 128), 256, GEMM_SMEM_BYTES>>>(
        ctx_p, wouth_p, b_out, out, M_, D_, D_);
}